// round 1
// baseline (speedup 1.0000x reference)
#include <cuda_runtime.h>
#include <cuda_bf16.h>

#define NUM_CLASSES 16384
#define FEAT_DIM    1024
#define ALPHA       0.5f

// Scratch (no cudaMalloc allowed)
__device__ int    g_counts[NUM_CLASSES];
__device__ double g_acc;

// ---------------------------------------------------------------------------
// Kernel 0: zero counts + accumulator (must run every graph replay)
// ---------------------------------------------------------------------------
__global__ void zero_kernel() {
    int idx = blockIdx.x * blockDim.x + threadIdx.x;
    if (idx < NUM_CLASSES) g_counts[idx] = 0;
    if (idx == 0) g_acc = 0.0;
}

// ---------------------------------------------------------------------------
// Kernel 1: bincount
// ---------------------------------------------------------------------------
__global__ void bincount_kernel(const int* __restrict__ y_true) {
    int idx = blockIdx.x * blockDim.x + threadIdx.x;
    if (idx < NUM_CLASSES) {
        atomicAdd(&g_counts[y_true[idx]], 1);
    }
}

// ---------------------------------------------------------------------------
// Kernel 2: main fused center-loss
// One block per sample row. 256 threads x float4 = 1024 floats.
//   j  = y_true[i], jj = y_true[j]
//   d  = y_pred[i] - centers[j] + (ALPHA/(counts[jj]+1)) * (centers[jj] - y_pred[j])
//   acc += sum(d*d)
// ---------------------------------------------------------------------------
__global__ __launch_bounds__(256)
void centerloss_kernel(const int*   __restrict__ y_true,
                       const float* __restrict__ y_pred,
                       const float* __restrict__ centers) {
    const int row = blockIdx.x;
    const int tid = threadIdx.x;

    // scalar indices (broadcast loads, L1-cached)
    const int j  = y_true[row];
    const int jj = y_true[j];
    const float scale = ALPHA / ((float)g_counts[jj] + 1.0f);

    const float4* yp_i = (const float4*)(y_pred  + (size_t)row * FEAT_DIM);
    const float4* c_j  = (const float4*)(centers + (size_t)j   * FEAT_DIM);
    const float4* c_jj = (const float4*)(centers + (size_t)jj  * FEAT_DIM);
    const float4* yp_j = (const float4*)(y_pred  + (size_t)j   * FEAT_DIM);

    // 256 threads * 4 floats = 1024 = FEAT_DIM  (one float4 per thread)
    float4 a = yp_i[tid];
    float4 b = c_j[tid];
    float4 c = c_jj[tid];
    float4 d = yp_j[tid];

    float dx = a.x - b.x + scale * (c.x - d.x);
    float dy = a.y - b.y + scale * (c.y - d.y);
    float dz = a.z - b.z + scale * (c.z - d.z);
    float dw = a.w - b.w + scale * (c.w - d.w);

    float s = dx*dx + dy*dy + dz*dz + dw*dw;

    // warp reduce
    #pragma unroll
    for (int off = 16; off > 0; off >>= 1)
        s += __shfl_xor_sync(0xFFFFFFFFu, s, off);

    // block reduce via smem (8 warps)
    __shared__ float warp_sums[8];
    const int wid = tid >> 5;
    const int lid = tid & 31;
    if (lid == 0) warp_sums[wid] = s;
    __syncthreads();

    if (wid == 0) {
        float v = (lid < 8) ? warp_sums[lid] : 0.0f;
        #pragma unroll
        for (int off = 4; off > 0; off >>= 1)
            v += __shfl_xor_sync(0xFFFFFFFFu, v, off);
        if (lid == 0) atomicAdd(&g_acc, (double)v);
    }
}

// ---------------------------------------------------------------------------
// Kernel 3: finalize
// ---------------------------------------------------------------------------
__global__ void finalize_kernel(float* __restrict__ out) {
    out[0] = (float)(g_acc / ((double)NUM_CLASSES * (double)FEAT_DIM));
}

extern "C" void kernel_launch(void* const* d_in, const int* in_sizes, int n_in,
                              void* d_out, int out_size) {
    const int*   y_true  = (const int*)  d_in[0];
    const float* y_pred  = (const float*)d_in[1];
    const float* centers = (const float*)d_in[2];
    float* out = (float*)d_out;

    zero_kernel<<<(NUM_CLASSES + 255) / 256, 256>>>();
    bincount_kernel<<<(NUM_CLASSES + 255) / 256, 256>>>(y_true);
    centerloss_kernel<<<NUM_CLASSES, 256>>>(y_true, y_pred, centers);
    finalize_kernel<<<1, 1>>>(out);
}